// round 14
// baseline (speedup 1.0000x reference)
#include <cuda_runtime.h>
#include <math.h>

#define BROWS 16384
#define DCOLS 2048
#define INV_LOG_D 0.13115409961775f   // 1/log(2048)

// Scratch (no allocations allowed)
__device__ float g_disp[BROWS];
__device__ float g_tot[BROWS];
__device__ float g_minf[BROWS];
__device__ float g_maxf[BROWS];
__device__ float g_rowc[BROWS];
__device__ float g_scal[4];   // [0]=invM, [1]=gmin(combined), [2]=scale

__device__ __forceinline__ float warp_sum(float v) {
#pragma unroll
    for (int o = 16; o; o >>= 1) v += __shfl_xor_sync(0xffffffffu, v, o);
    return v;
}
__device__ __forceinline__ float warp_min(float v) {
#pragma unroll
    for (int o = 16; o; o >>= 1) v = fminf(v, __shfl_xor_sync(0xffffffffu, v, o));
    return v;
}
__device__ __forceinline__ float warp_max(float v) {
#pragma unroll
    for (int o = 16; o; o >>= 1) v = fmaxf(v, __shfl_xor_sync(0xffffffffu, v, o));
    return v;
}

// fast sigmoid — MUST be identical in k_global and k_final (min/max consistency)
__device__ __forceinline__ float sigm(float x) {
    return 1.0f / (1.0f + __expf(-x));
}

// ---------------------------------------------------------------------------
// Kernel 1: per-row statistics. 256 threads/row; each thread owns two
// 4-element chunks (float4 at t and t+256) -> 4 independent coalesced
// LDG.128 front-batched (MLP=4). Edge exchange over 512 chunk slots.
// Circular gradient mean is exactly 0 -> var = sum(g^2)/(n-1).
// ---------------------------------------------------------------------------
__global__ __launch_bounds__(256) void k_rowstats(
    const float* __restrict__ psi, const float* __restrict__ field)
{
    __shared__ float spL[512], spR[512];   // psi chunk edges (first, last elem)
    __shared__ float sfL[512], sfR[512];   // field chunk edges
    __shared__ float red[5][8];
    __shared__ float redmn[8], redmx[8];

    const int row = blockIdx.x;
    const int t = threadIdx.x;
    const size_t base = (size_t)row * DCOLS;
    const float4* P = reinterpret_cast<const float4*>(psi + base);
    const float4* F = reinterpret_cast<const float4*>(field + base);

    // 4 independent coalesced loads, front-batched
    float4 pa = P[t];
    float4 pb = P[t + 256];
    float4 fa = F[t];
    float4 fb = F[t + 256];

    // chunk ids: ca = t, cb = 256 + t (512 chunks of 4 elems circular)
    spL[t] = pa.x;        spR[t] = pa.w;
    spL[256 + t] = pb.x;  spR[256 + t] = pb.w;
    sfL[t] = fa.x;        sfR[t] = fa.w;
    sfL[256 + t] = fb.x;  sfR[256 + t] = fb.w;

    // elementwise stats over 8 psi elems / 8 field elems
    float pl, ps, ps2, mn, mx;
    {
        float p0 = pa.x, p1 = pa.y, p2 = pa.z, p3 = pa.w;
        float p4 = pb.x, p5 = pb.y, p6 = pb.z, p7 = pb.w;
        pl = p0 * __logf(p0 + 1e-10f) + p1 * __logf(p1 + 1e-10f)
           + p2 * __logf(p2 + 1e-10f) + p3 * __logf(p3 + 1e-10f)
           + p4 * __logf(p4 + 1e-10f) + p5 * __logf(p5 + 1e-10f)
           + p6 * __logf(p6 + 1e-10f) + p7 * __logf(p7 + 1e-10f);
        ps  = ((p0 + p1) + (p2 + p3)) + ((p4 + p5) + (p6 + p7));
        ps2 = ((p0 * p0 + p1 * p1) + (p2 * p2 + p3 * p3))
            + ((p4 * p4 + p5 * p5) + (p6 * p6 + p7 * p7));
        float a0 = fabsf(fa.x), a1 = fabsf(fa.y), a2 = fabsf(fa.z), a3 = fabsf(fa.w);
        float a4 = fabsf(fb.x), a5 = fabsf(fb.y), a6 = fabsf(fb.z), a7 = fabsf(fb.w);
        mn = fminf(fminf(fminf(a0, a1), fminf(a2, a3)),
                   fminf(fminf(a4, a5), fminf(a6, a7)));
        mx = fmaxf(fmaxf(fmaxf(a0, a1), fmaxf(a2, a3)),
                   fmaxf(fmaxf(a4, a5), fmaxf(a6, a7)));
    }
    __syncthreads();

    // gradients: chunk ca = t, chunk cb = 256 + t
    float gs2, hs2;
    {
        const int ca = t, cb = 256 + t;
        float pA_prev = spR[(ca - 1) & 511], pA_next = spL[(ca + 1) & 511];
        float pB_prev = spR[(cb - 1) & 511], pB_next = spL[(cb + 1) & 511];
        float fA_prev = sfR[(ca - 1) & 511], fA_next = sfL[(ca + 1) & 511];
        float fB_prev = sfR[(cb - 1) & 511], fB_next = sfL[(cb + 1) & 511];

        float g0 = pa.y - pA_prev;
        float g1 = pa.z - pa.x;
        float g2 = pa.w - pa.y;
        float g3 = pA_next - pa.z;
        float g4 = pb.y - pB_prev;
        float g5 = pb.z - pb.x;
        float g6 = pb.w - pb.y;
        float g7 = pB_next - pb.z;
        gs2 = 0.25f * (((g0 * g0 + g1 * g1) + (g2 * g2 + g3 * g3))
                     + ((g4 * g4 + g5 * g5) + (g6 * g6 + g7 * g7)));

        float h0 = fa.y - fA_prev;
        float h1 = fa.z - fa.x;
        float h2 = fa.w - fa.y;
        float h3 = fA_next - fa.z;
        float h4 = fb.y - fB_prev;
        float h5 = fb.z - fb.x;
        float h6 = fb.w - fb.y;
        float h7 = fB_next - fb.z;
        hs2 = 0.25f * (((h0 * h0 + h1 * h1) + (h2 * h2 + h3 * h3))
                     + ((h4 * h4 + h5 * h5) + (h6 * h6 + h7 * h7)));
    }

    // block reduction: 5 sums + min + max (8 warps)
    pl = warp_sum(pl);  ps = warp_sum(ps);  ps2 = warp_sum(ps2);
    gs2 = warp_sum(gs2);  hs2 = warp_sum(hs2);
    mn = warp_min(mn);  mx = warp_max(mx);

    const int wid = t >> 5, lane = t & 31;
    if (lane == 0) {
        red[0][wid] = pl;  red[1][wid] = ps;  red[2][wid] = ps2;
        red[3][wid] = gs2; red[4][wid] = hs2;
        redmn[wid] = mn;   redmx[wid] = mx;
    }
    __syncthreads();

    if (t == 0) {
        float a0 = 0.f, a1 = 0.f, a2 = 0.f, a3 = 0.f, a4 = 0.f;
        float amn = 1e30f, amx = 0.f;
#pragma unroll
        for (int i = 0; i < 8; i++) {
            a0 += red[0][i]; a1 += red[1][i]; a2 += red[2][i];
            a3 += red[3][i]; a4 += red[4][i];
            amn = fminf(amn, redmn[i]);
            amx = fmaxf(amx, redmx[i]);
        }
        const float n = (float)DCOLS;
        const float inv_nm1 = 1.0f / (n - 1.0f);

        float mean = a1 / n;
        float var = fmaxf((a2 - a1 * mean) * inv_nm1, 0.f);   // unbiased
        float pstd = sqrtf(var);
        float norm_ent = (-a0) * INV_LOG_D;
        float disp = fminf(fmaxf(0.7f * norm_ent + 0.3f * pstd, 0.f), 1.f);

        // circular gradient has exactly zero mean -> var = sum(g^2)/(n-1)
        float gvar = a3 * inv_nm1;
        float hvar = a4 * inv_nm1;
        float tot = sqrtf(gvar + hvar);

        g_disp[row] = disp;
        g_tot[row]  = tot;
        g_minf[row] = amn;
        g_maxf[row] = amx;
    }
}

// ---------------------------------------------------------------------------
// Kernel 2: single block. Global M = max|field|, maxtot; per-row constant;
// global min/max of combined via sigmoid monotonicity on per-row min/max |f|.
// ---------------------------------------------------------------------------
__global__ __launch_bounds__(1024) void k_global(const float* __restrict__ w)
{
    __shared__ float s1[32], s2[32];
    __shared__ float sM, sT;
    const int t = threadIdx.x;
    const int wid = t >> 5, lane = t & 31;

    float m1 = 0.f, m2 = 0.f;
    for (int i = t; i < BROWS; i += 1024) {
        m1 = fmaxf(m1, g_maxf[i]);
        m2 = fmaxf(m2, g_tot[i]);
    }
    m1 = warp_max(m1);
    m2 = warp_max(m2);
    if (lane == 0) { s1[wid] = m1; s2[wid] = m2; }
    __syncthreads();
    if (t == 0) {
        float M = 0.f, T = 0.f;
#pragma unroll
        for (int i = 0; i < 32; i++) { M = fmaxf(M, s1[i]); T = fmaxf(T, s2[i]); }
        sM = M; sT = T;
    }
    __syncthreads();

    const float invM = 1.0f / (sM + 1e-10f);
    const float invT = 1.0f / (sT + 1e-10f);
    const float w0 = w[0], w1 = w[1], w2 = w[2], w3 = w[3];

    float cmn = 1e30f, cmx = -1e30f;
    for (int i = t; i < BROWS; i += 1024) {
        float comp = fminf(fmaxf(g_tot[i] * invT, 0.f), 1.f);
        float rc = w0 * g_disp[i] + w2 * comp + w3 * 0.5f;
        g_rowc[i] = rc;
        // same expression as kernel 3 for consistent extremes
        float ffa = sigm(5.0f * (g_minf[i] * invM - 0.5f));
        float ffb = sigm(5.0f * (g_maxf[i] * invM - 0.5f));
        float lo = (w1 >= 0.f) ? ffa : ffb;
        float hi = (w1 >= 0.f) ? ffb : ffa;
        cmn = fminf(cmn, rc + w1 * lo);
        cmx = fmaxf(cmx, rc + w1 * hi);
    }
    cmn = warp_min(cmn);
    cmx = warp_max(cmx);
    if (lane == 0) { s1[wid] = cmn; s2[wid] = cmx; }
    __syncthreads();
    if (t == 0) {
        float gmn = 1e30f, gmx = -1e30f;
#pragma unroll
        for (int i = 0; i < 32; i++) { gmn = fminf(gmn, s1[i]); gmx = fmaxf(gmx, s2[i]); }
        g_scal[0] = invM;
        g_scal[1] = gmn;
        g_scal[2] = 0.099f / (gmx - gmn + 1e-10f);   // (D_MAX-D_MIN)/range
    }
}

// ---------------------------------------------------------------------------
// Kernel 3: finalize — warp-shuffle neighbor exchange, no smem, no barrier.
// Each warp owns 128 consecutive chunks (4 groups of 32, lane <-> chunk).
// 512 chunks/row and 32|512 -> a group never crosses a row boundary.
// Own dc computed once (4 sigmoids/chunk); smoothing neighbors come from
// __shfl of d3/d0. Only lanes 0/31 do one scalar field load (front-batched)
// and recompute the boundary dc with the identical expression.
// ---------------------------------------------------------------------------
__global__ __launch_bounds__(256) void k_final(
    const float* __restrict__ field, const float* __restrict__ w,
    float* __restrict__ out)
{
    const int t = threadIdx.x;
    const int lane = t & 31;
    const int wid = t >> 5;
    const int wbase = blockIdx.x * 1024 + wid * 128;   // warp's first chunk

    const float invM = g_scal[0];
    const float gmn  = g_scal[1];
    const float sc   = g_scal[2];
    const float w1   = w[1];

    float4 v[4];
    float fedge[4];   // lane 0: prev field elem; lane 31: next field elem
    float rcv[4];
#pragma unroll
    for (int k = 0; k < 4; k++) {
        const int c = wbase + k * 32 + lane;
        const int row = c >> 9;                 // 512 chunks per row
        const int jc = (c & 511) << 2;          // element offset within row
        const float* rowp = field + ((size_t)row << 11);
        v[k] = reinterpret_cast<const float4*>(rowp)[c & 511];
        if (lane == 0)       fedge[k] = rowp[(jc - 1) & 2047];   // circular prev
        else if (lane == 31) fedge[k] = rowp[(jc + 4) & 2047];   // circular next
        rcv[k] = g_rowc[row];
    }

#pragma unroll
    for (int k = 0; k < 4; k++) {
        const int c = wbase + k * 32 + lane;
        const float rc = rcv[k];

        float d0, d1, d2, d3;
        {
            float a0 = fabsf(v[k].x), a1 = fabsf(v[k].y);
            float a2 = fabsf(v[k].z), a3 = fabsf(v[k].w);
            d0 = 0.001f + (rc + w1 * sigm(5.0f * (a0 * invM - 0.5f)) - gmn) * sc;
            d1 = 0.001f + (rc + w1 * sigm(5.0f * (a1 * invM - 0.5f)) - gmn) * sc;
            d2 = 0.001f + (rc + w1 * sigm(5.0f * (a2 * invM - 0.5f)) - gmn) * sc;
            d3 = 0.001f + (rc + w1 * sigm(5.0f * (a3 * invM - 0.5f)) - gmn) * sc;
        }

        float dprev = __shfl_up_sync(0xffffffffu, d3, 1);
        float dnext = __shfl_down_sync(0xffffffffu, d0, 1);
        if (lane == 0 || lane == 31) {
            float a = fabsf(fedge[k]);
            float de = 0.001f + (rc + w1 * sigm(5.0f * (a * invM - 0.5f)) - gmn) * sc;
            if (lane == 0) dprev = de; else dnext = de;
        }

        float4 ov;
        ov.x = 0.25f * dprev + 0.5f * d0 + 0.25f * d1;
        ov.y = 0.25f * d0 + 0.5f * d1 + 0.25f * d2;
        ov.z = 0.25f * d1 + 0.5f * d2 + 0.25f * d3;
        ov.w = 0.25f * d2 + 0.5f * d3 + 0.25f * dnext;
        reinterpret_cast<float4*>(out)[c] = ov;
    }
}

// ---------------------------------------------------------------------------
extern "C" void kernel_launch(void* const* d_in, const int* in_sizes, int n_in,
                              void* d_out, int out_size)
{
    const float* psi   = (const float*)d_in[0];
    const float* field = (const float*)d_in[1];
    const float* w     = (const float*)d_in[2];
    float* out = (float*)d_out;

    k_rowstats<<<BROWS, 256>>>(psi, field);
    k_global<<<1, 1024>>>(w);
    // total chunks = BROWS*512 = 8388608; 1024 chunks/block -> 8192 blocks
    k_final<<<8192, 256>>>(field, w, out);
}

// round 15
// speedup vs baseline: 1.1956x; 1.1956x over previous
#include <cuda_runtime.h>
#include <math.h>

#define BROWS 16384
#define DCOLS 2048
#define INV_LOG_D 0.13115409961775f   // 1/log(2048)

// Scratch (no allocations allowed)
__device__ float g_disp[BROWS];
__device__ float g_tot[BROWS];
__device__ float g_minf[BROWS];
__device__ float g_maxf[BROWS];
__device__ float g_rowc[BROWS];
__device__ float g_scal[4];   // [0]=invM, [1]=gmin(combined), [2]=scale

__device__ __forceinline__ float warp_sum(float v) {
#pragma unroll
    for (int o = 16; o; o >>= 1) v += __shfl_xor_sync(0xffffffffu, v, o);
    return v;
}
__device__ __forceinline__ float warp_min(float v) {
#pragma unroll
    for (int o = 16; o; o >>= 1) v = fminf(v, __shfl_xor_sync(0xffffffffu, v, o));
    return v;
}
__device__ __forceinline__ float warp_max(float v) {
#pragma unroll
    for (int o = 16; o; o >>= 1) v = fmaxf(v, __shfl_xor_sync(0xffffffffu, v, o));
    return v;
}

// fast sigmoid — MUST be identical in k_global and k_final (min/max consistency)
// __fdividef: single MUFU.RCP instead of the IEEE division subroutine.
__device__ __forceinline__ float sigm(float x) {
    return __fdividef(1.0f, 1.0f + __expf(-x));
}

// ---------------------------------------------------------------------------
// Kernel 1: per-row statistics. 256 threads/row; 4 front-batched LDG.128.
// psi loaded with __ldcs (evict-first: never re-read) so L2 preferentially
// retains field (128MB vs ~126MB L2) for k_final's second pass.
// ---------------------------------------------------------------------------
__global__ __launch_bounds__(256) void k_rowstats(
    const float* __restrict__ psi, const float* __restrict__ field)
{
    __shared__ float spL[512], spR[512];   // psi chunk edges (first, last elem)
    __shared__ float sfL[512], sfR[512];   // field chunk edges
    __shared__ float red[5][8];
    __shared__ float redmn[8], redmx[8];

    const int row = blockIdx.x;
    const int t = threadIdx.x;
    const size_t base = (size_t)row * DCOLS;
    const float4* P = reinterpret_cast<const float4*>(psi + base);
    const float4* F = reinterpret_cast<const float4*>(field + base);

    // 4 independent coalesced loads, front-batched
    float4 pa = __ldcs(P + t);         // psi: streaming (no reuse)
    float4 pb = __ldcs(P + t + 256);
    float4 fa = F[t];                  // field: default (retain in L2)
    float4 fb = F[t + 256];

    // chunk ids: ca = t, cb = 256 + t (512 chunks of 4 elems circular)
    spL[t] = pa.x;        spR[t] = pa.w;
    spL[256 + t] = pb.x;  spR[256 + t] = pb.w;
    sfL[t] = fa.x;        sfR[t] = fa.w;
    sfL[256 + t] = fb.x;  sfR[256 + t] = fb.w;

    // elementwise stats over 8 psi elems / 8 field elems
    float pl, ps, ps2, mn, mx;
    {
        float p0 = pa.x, p1 = pa.y, p2 = pa.z, p3 = pa.w;
        float p4 = pb.x, p5 = pb.y, p6 = pb.z, p7 = pb.w;
        pl = p0 * __logf(p0 + 1e-10f) + p1 * __logf(p1 + 1e-10f)
           + p2 * __logf(p2 + 1e-10f) + p3 * __logf(p3 + 1e-10f)
           + p4 * __logf(p4 + 1e-10f) + p5 * __logf(p5 + 1e-10f)
           + p6 * __logf(p6 + 1e-10f) + p7 * __logf(p7 + 1e-10f);
        ps  = ((p0 + p1) + (p2 + p3)) + ((p4 + p5) + (p6 + p7));
        ps2 = ((p0 * p0 + p1 * p1) + (p2 * p2 + p3 * p3))
            + ((p4 * p4 + p5 * p5) + (p6 * p6 + p7 * p7));
        float a0 = fabsf(fa.x), a1 = fabsf(fa.y), a2 = fabsf(fa.z), a3 = fabsf(fa.w);
        float a4 = fabsf(fb.x), a5 = fabsf(fb.y), a6 = fabsf(fb.z), a7 = fabsf(fb.w);
        mn = fminf(fminf(fminf(a0, a1), fminf(a2, a3)),
                   fminf(fminf(a4, a5), fminf(a6, a7)));
        mx = fmaxf(fmaxf(fmaxf(a0, a1), fmaxf(a2, a3)),
                   fmaxf(fmaxf(a4, a5), fmaxf(a6, a7)));
    }
    __syncthreads();

    // gradients: chunk ca = t, chunk cb = 256 + t
    float gs2, hs2;
    {
        const int ca = t, cb = 256 + t;
        float pA_prev = spR[(ca - 1) & 511], pA_next = spL[(ca + 1) & 511];
        float pB_prev = spR[(cb - 1) & 511], pB_next = spL[(cb + 1) & 511];
        float fA_prev = sfR[(ca - 1) & 511], fA_next = sfL[(ca + 1) & 511];
        float fB_prev = sfR[(cb - 1) & 511], fB_next = sfL[(cb + 1) & 511];

        float g0 = pa.y - pA_prev;
        float g1 = pa.z - pa.x;
        float g2 = pa.w - pa.y;
        float g3 = pA_next - pa.z;
        float g4 = pb.y - pB_prev;
        float g5 = pb.z - pb.x;
        float g6 = pb.w - pb.y;
        float g7 = pB_next - pb.z;
        gs2 = 0.25f * (((g0 * g0 + g1 * g1) + (g2 * g2 + g3 * g3))
                     + ((g4 * g4 + g5 * g5) + (g6 * g6 + g7 * g7)));

        float h0 = fa.y - fA_prev;
        float h1 = fa.z - fa.x;
        float h2 = fa.w - fa.y;
        float h3 = fA_next - fa.z;
        float h4 = fb.y - fB_prev;
        float h5 = fb.z - fb.x;
        float h6 = fb.w - fb.y;
        float h7 = fB_next - fb.z;
        hs2 = 0.25f * (((h0 * h0 + h1 * h1) + (h2 * h2 + h3 * h3))
                     + ((h4 * h4 + h5 * h5) + (h6 * h6 + h7 * h7)));
    }

    // block reduction: 5 sums + min + max (8 warps)
    pl = warp_sum(pl);  ps = warp_sum(ps);  ps2 = warp_sum(ps2);
    gs2 = warp_sum(gs2);  hs2 = warp_sum(hs2);
    mn = warp_min(mn);  mx = warp_max(mx);

    const int wid = t >> 5, lane = t & 31;
    if (lane == 0) {
        red[0][wid] = pl;  red[1][wid] = ps;  red[2][wid] = ps2;
        red[3][wid] = gs2; red[4][wid] = hs2;
        redmn[wid] = mn;   redmx[wid] = mx;
    }
    __syncthreads();

    if (t == 0) {
        float a0 = 0.f, a1 = 0.f, a2 = 0.f, a3 = 0.f, a4 = 0.f;
        float amn = 1e30f, amx = 0.f;
#pragma unroll
        for (int i = 0; i < 8; i++) {
            a0 += red[0][i]; a1 += red[1][i]; a2 += red[2][i];
            a3 += red[3][i]; a4 += red[4][i];
            amn = fminf(amn, redmn[i]);
            amx = fmaxf(amx, redmx[i]);
        }
        const float n = (float)DCOLS;
        const float inv_nm1 = 1.0f / (n - 1.0f);

        float mean = a1 / n;
        float var = fmaxf((a2 - a1 * mean) * inv_nm1, 0.f);   // unbiased
        float pstd = sqrtf(var);
        float norm_ent = (-a0) * INV_LOG_D;
        float disp = fminf(fmaxf(0.7f * norm_ent + 0.3f * pstd, 0.f), 1.f);

        // circular gradient has exactly zero mean -> var = sum(g^2)/(n-1)
        float gvar = a3 * inv_nm1;
        float hvar = a4 * inv_nm1;
        float tot = sqrtf(gvar + hvar);

        g_disp[row] = disp;
        g_tot[row]  = tot;
        g_minf[row] = amn;
        g_maxf[row] = amx;
    }
}

// ---------------------------------------------------------------------------
// Kernel 2: single block. Global M = max|field|, maxtot; per-row constant;
// global min/max of combined via sigmoid monotonicity on per-row min/max |f|.
// ---------------------------------------------------------------------------
__global__ __launch_bounds__(1024) void k_global(const float* __restrict__ w)
{
    __shared__ float s1[32], s2[32];
    __shared__ float sM, sT;
    const int t = threadIdx.x;
    const int wid = t >> 5, lane = t & 31;

    float m1 = 0.f, m2 = 0.f;
    for (int i = t; i < BROWS; i += 1024) {
        m1 = fmaxf(m1, g_maxf[i]);
        m2 = fmaxf(m2, g_tot[i]);
    }
    m1 = warp_max(m1);
    m2 = warp_max(m2);
    if (lane == 0) { s1[wid] = m1; s2[wid] = m2; }
    __syncthreads();
    if (t == 0) {
        float M = 0.f, T = 0.f;
#pragma unroll
        for (int i = 0; i < 32; i++) { M = fmaxf(M, s1[i]); T = fmaxf(T, s2[i]); }
        sM = M; sT = T;
    }
    __syncthreads();

    const float invM = 1.0f / (sM + 1e-10f);
    const float invT = 1.0f / (sT + 1e-10f);
    const float w0 = w[0], w1 = w[1], w2 = w[2], w3 = w[3];

    float cmn = 1e30f, cmx = -1e30f;
    for (int i = t; i < BROWS; i += 1024) {
        float comp = fminf(fmaxf(g_tot[i] * invT, 0.f), 1.f);
        float rc = w0 * g_disp[i] + w2 * comp + w3 * 0.5f;
        g_rowc[i] = rc;
        // same expression as kernel 3 for consistent extremes
        float ffa = sigm(5.0f * (g_minf[i] * invM - 0.5f));
        float ffb = sigm(5.0f * (g_maxf[i] * invM - 0.5f));
        float lo = (w1 >= 0.f) ? ffa : ffb;
        float hi = (w1 >= 0.f) ? ffb : ffa;
        cmn = fminf(cmn, rc + w1 * lo);
        cmx = fmaxf(cmx, rc + w1 * hi);
    }
    cmn = warp_min(cmn);
    cmx = warp_max(cmx);
    if (lane == 0) { s1[wid] = cmn; s2[wid] = cmx; }
    __syncthreads();
    if (t == 0) {
        float gmn = 1e30f, gmx = -1e30f;
#pragma unroll
        for (int i = 0; i < 32; i++) { gmn = fminf(gmn, s1[i]); gmx = fmaxf(gmx, s2[i]); }
        g_scal[0] = invM;
        g_scal[1] = gmn;
        g_scal[2] = 0.099f / (gmx - gmn + 1e-10f);   // (D_MAX-D_MIN)/range
    }
}

// ---------------------------------------------------------------------------
// Kernel 3: finalize — R6 structure (measured best): 128 threads/row, four
// front-batched LDG.128 per thread, smem chunk-edge exchange, one barrier.
// field loads __ldcs (hit L2 lines retained from k_rowstats, evict after);
// out stores __stcs (don't evict not-yet-read field lines).
// ---------------------------------------------------------------------------
__global__ __launch_bounds__(128) void k_final(
    const float* __restrict__ field, const float* __restrict__ w,
    float* __restrict__ out)
{
    __shared__ float sdL[512], sdR[512];
    const int row = blockIdx.x;
    const int t = threadIdx.x;
    const size_t base = (size_t)row * DCOLS;
    const float4* F = reinterpret_cast<const float4*>(field + base);

    const float invM = g_scal[0];
    const float gmn  = g_scal[1];
    const float sc   = g_scal[2];
    const float rc   = g_rowc[row];
    const float w1   = w[1];

    // 4 independent coalesced loads, front-batched
    float4 v0 = __ldcs(F + t);
    float4 v1 = __ldcs(F + t + 128);
    float4 v2 = __ldcs(F + t + 256);
    float4 v3 = __ldcs(F + t + 384);

    float de[16];
    {
        float fe[16] = {v0.x, v0.y, v0.z, v0.w,  v1.x, v1.y, v1.z, v1.w,
                        v2.x, v2.y, v2.z, v2.w,  v3.x, v3.y, v3.z, v3.w};
#pragma unroll
        for (int k = 0; k < 16; k++) {
            float a = fabsf(fe[k]);
            float ff = sigm(5.0f * (a * invM - 0.5f));
            float c = rc + w1 * ff;
            de[k] = 0.001f + (c - gmn) * sc;
        }
    }
    // chunk c = t + 128*k owns de[4k..4k+4)
#pragma unroll
    for (int k = 0; k < 4; k++) {
        sdL[t + 128 * k] = de[4 * k];
        sdR[t + 128 * k] = de[4 * k + 3];
    }
    __syncthreads();

    float4* O = reinterpret_cast<float4*>(out + base);
#pragma unroll
    for (int k = 0; k < 4; k++) {
        const int c = t + 128 * k;
        const float d_prev = sdR[(c - 1) & 511];
        const float d_next = sdL[(c + 1) & 511];
        const float e0 = de[4 * k], e1 = de[4 * k + 1];
        const float e2 = de[4 * k + 2], e3 = de[4 * k + 3];
        float4 ov;
        ov.x = 0.25f * d_prev + 0.5f * e0 + 0.25f * e1;
        ov.y = 0.25f * e0 + 0.5f * e1 + 0.25f * e2;
        ov.z = 0.25f * e1 + 0.5f * e2 + 0.25f * e3;
        ov.w = 0.25f * e2 + 0.5f * e3 + 0.25f * d_next;
        __stcs(O + c, ov);
    }
}

// ---------------------------------------------------------------------------
extern "C" void kernel_launch(void* const* d_in, const int* in_sizes, int n_in,
                              void* d_out, int out_size)
{
    const float* psi   = (const float*)d_in[0];
    const float* field = (const float*)d_in[1];
    const float* w     = (const float*)d_in[2];
    float* out = (float*)d_out;

    k_rowstats<<<BROWS, 256>>>(psi, field);
    k_global<<<1, 1024>>>(w);
    k_final<<<BROWS, 128>>>(field, w, out);
}